// round 1
// baseline (speedup 1.0000x reference)
#include <cuda_runtime.h>
#include <cuda_fp16.h>
#include <cstdint>
#include <cstddef>

// ---------------------------------------------------------------------------
// Problem constants (fixed-shape problem)
// ---------------------------------------------------------------------------
namespace {
constexpr int BATCH = 8;
constexpr int FI    = 256;
constexpr int FO    = 512;
constexpr int HW    = 256;     // input H = W
constexpr int OHW   = 128;     // output H = W
constexpr int KTOT  = FI * 9;  // 2304, GEMM K
constexpr int CH    = BATCH * FI;  // 2048 depthwise channels
constexpr int PROWS = 129;     // phase-plane rows (h2 = 0..128)
constexpr int PW    = 128;     // phase-plane cols (w2 = 0..127)
constexpr size_t PLANE = (size_t)CH * PROWS * PW;  // elems per (kw,a) plane
}

// Scratch (device globals; no cudaMalloc allowed).
// g_P[pi][ch][h2][w2], pi = kw*2 + (h&1):  P = Y[2*h2 + a][2*w2 + kw]
__device__ __half g_P[6 * PLANE];            // ~406 MB fp16
__device__ __half g_Wh[(size_t)FO * KTOT];   // w * (1/48) in fp16

// ---------------------------------------------------------------------------
// Pass 1: depthwise 4x4 FIR (pad 2) -> phase planes (fp16)
// Y[h][w] = sum_{i,j} fir[i][j] * x[h-2+i][w-2+j], h,w in [0,257)
// grid (33, 2048), block 256. Each block: one channel, 8 output rows.
// ---------------------------------------------------------------------------
__device__ __forceinline__ void write_phase(int ch, int h, int w, float y) {
    __half hv = __float2half_rn(y);
    int a  = h & 1;
    int h2 = h >> 1;
    size_t rowbase = ((size_t)ch * PROWS + h2) * PW;
    if (!(w & 1)) {
        int w2 = w >> 1;
        if (w2 < PW) g_P[(size_t)(0 + a) * PLANE + rowbase + w2] = hv;       // kw=0
        if (w >= 2)  g_P[(size_t)(4 + a) * PLANE + rowbase + (w2 - 1)] = hv; // kw=2
    } else {
        g_P[(size_t)(2 + a) * PLANE + rowbase + (w >> 1)] = hv;              // kw=1
    }
}

__global__ void fir_kernel(const float* __restrict__ x,
                           const float* __restrict__ fir) {
    const int w  = threadIdx.x;      // 0..255 (column)
    const int ch = blockIdx.y;       // 0..2047
    const int h0 = blockIdx.x * 8;

    __shared__ float Vb[2][264];

    // 1-D taps from row sums (fir = f1d outer f1d, sum(f1d)=1)
    const float f0 = fir[0]  + fir[1]  + fir[2]  + fir[3];
    const float f1 = fir[4]  + fir[5]  + fir[6]  + fir[7];
    const float f2 = fir[8]  + fir[9]  + fir[10] + fir[11];
    const float f3 = fir[12] + fir[13] + fir[14] + fir[15];

    const float* xc = x + (size_t)ch * (HW * HW);
    auto ldrow = [&](int h) -> float {
        return (h >= 0 && h < HW) ? __ldg(xc + h * HW + w) : 0.0f;
    };

    float r0 = ldrow(h0 - 2);
    float r1 = ldrow(h0 - 1);
    float r2 = ldrow(h0);

    #pragma unroll
    for (int r = 0; r < 8; r++) {
        const int h = h0 + r;
        if (h > 256) break;  // uniform per block
        const float r3 = ldrow(h + 1);
        const float V  = f0 * r0 + f1 * r1 + f2 * r2 + f3 * r3;  // vertical FIR
        float* vb = Vb[r & 1];
        vb[w + 2] = V;
        if (w < 2) { vb[w] = 0.0f; vb[258 + w] = 0.0f; }
        __syncthreads();
        // horizontal FIR: Y[w] = sum_j f[j] * V[w-2+j]
        const float y = f0 * vb[w] + f1 * vb[w + 1] + f2 * vb[w + 2] + f3 * vb[w + 3];
        write_phase(ch, h, w, y);
        if (w == 0) {
            const float y2 = f0 * vb[256] + f1 * vb[257] + f2 * vb[258] + f3 * vb[259];
            write_phase(ch, h, 256, y2);
        }
        r0 = r1; r1 = r2; r2 = r3;
    }
}

// ---------------------------------------------------------------------------
// Pass 1b: weights -> fp16, scaled by (FI*K*K)^-0.5 = 1/48
// ---------------------------------------------------------------------------
__global__ void wcvt_kernel(const float* __restrict__ w) {
    const int i = blockIdx.x * 256 + threadIdx.x;
    if (i < FO * KTOT) g_Wh[i] = __float2half_rn(w[i] * (1.0f / 48.0f));
}

// ---------------------------------------------------------------------------
// Pass 2: implicit GEMM conv.  C[fo][n] = sum_k A[fo][k] * B[k][n]
// k = fi*9 + kh*3 + kw ; n = ((b*128)+oh)*128+ow (one tile = one (b,oh) row)
// B[k][n] = g_P[kw*2 + (kh&1)][b*256+fi][oh + (kh>>1)][ow]   (unit stride!)
// Tile 128x128x32, 8 warps (2x4) of 64x32, mma.m16n8k16 f16->f32,
// 2-stage cp.async double buffer.
// ---------------------------------------------------------------------------
namespace {
constexpr int BM = 128, BN = 128, BK = 32;
constexpr int ASTRIDE = 40;    // halfs per A smem row (80B, 16B-aligned)
constexpr int BSTRIDE = 136;   // halfs per B smem row (272B)
constexpr int NK = KTOT / BK;  // 72
constexpr int A_STAGE_B = BM * ASTRIDE * 2;  // 10240 bytes
constexpr int B_STAGE_B = BK * BSTRIDE * 2;  // 8704 bytes
}

__device__ __forceinline__ void cp16(uint32_t s, const void* g) {
    asm volatile("cp.async.cg.shared.global [%0], [%1], 16;\n" :: "r"(s), "l"(g));
}
__device__ __forceinline__ void ldsm4(uint32_t (&r)[4], uint32_t a) {
    asm volatile("ldmatrix.sync.aligned.m8n8.x4.shared.b16 {%0,%1,%2,%3}, [%4];\n"
                 : "=r"(r[0]), "=r"(r[1]), "=r"(r[2]), "=r"(r[3]) : "r"(a));
}
__device__ __forceinline__ void ldsm4t(uint32_t (&r)[4], uint32_t a) {
    asm volatile("ldmatrix.sync.aligned.m8n8.x4.trans.shared.b16 {%0,%1,%2,%3}, [%4];\n"
                 : "=r"(r[0]), "=r"(r[1]), "=r"(r[2]), "=r"(r[3]) : "r"(a));
}
__device__ __forceinline__ void mma16816(float (&c)[4], const uint32_t (&a)[4],
                                         uint32_t b0, uint32_t b1) {
    asm volatile(
        "mma.sync.aligned.m16n8k16.row.col.f32.f16.f16.f32 "
        "{%0,%1,%2,%3}, {%4,%5,%6,%7}, {%8,%9}, {%0,%1,%2,%3};\n"
        : "+f"(c[0]), "+f"(c[1]), "+f"(c[2]), "+f"(c[3])
        : "r"(a[0]), "r"(a[1]), "r"(a[2]), "r"(a[3]), "r"(b0), "r"(b1));
}

__global__ __launch_bounds__(256, 2)
void conv_gemm_kernel(const float* __restrict__ bias, float* __restrict__ out) {
    __shared__ __half As[2][BM * ASTRIDE];
    __shared__ __half Bs[2][BK * BSTRIDE];

    const int tid  = threadIdx.x;
    const int lane = tid & 31;
    const int warp = tid >> 5;
    const int wm   = (warp & 1) * 64;   // warp M origin
    const int wn   = (warp >> 1) * 32;  // warp N origin

    const int m0 = blockIdx.x * BM;     // m fastest -> B-tile L2 reuse across 4 M-blocks
    const int nt = blockIdx.y;          // 0..1023
    const int bb = nt >> 7;
    const int oh = nt & 127;

    const uint32_t asmem = (uint32_t)__cvta_generic_to_shared(&As[0][0]);
    const uint32_t bsmem = (uint32_t)__cvta_generic_to_shared(&Bs[0][0]);

    // Per-thread copy slots (each thread: 32B of A, 32B of B per stage; no predication)
    const int a_row = tid >> 1;               // 0..127
    const int a_col = (tid & 1) * 16;         // halfs
    const __half* gA0 = g_Wh + (size_t)(m0 + a_row) * KTOT + a_col;
    const uint32_t sA0 = asmem + (uint32_t)(a_row * ASTRIDE + a_col) * 2;

    const int b_krow = tid >> 3;              // 0..31
    const int b_col  = (tid & 7) * 16;        // halfs
    const uint32_t sB0 = bsmem + (uint32_t)(b_krow * BSTRIDE + b_col) * 2;

    auto issue = [&](int buf, int kt) {
        const __half* ga = gA0 + kt * BK;
        const uint32_t sa = sA0 + buf * A_STAGE_B;
        cp16(sa,      ga);
        cp16(sa + 16, ga + 8);
        const int k  = kt * BK + b_krow;
        const int fi = k / 9;
        const int t9 = k - fi * 9;
        const int kh = t9 / 3;
        const int kw = t9 - kh * 3;
        const int pi = kw * 2 + (kh & 1);
        const __half* gb = g_P
            + (((size_t)pi * CH + (bb * FI + fi)) * PROWS + (oh + (kh >> 1))) * PW
            + b_col;
        const uint32_t sb = sB0 + buf * B_STAGE_B;
        cp16(sb,      gb);
        cp16(sb + 16, gb + 8);
        asm volatile("cp.async.commit_group;\n" ::: "memory");
    };

    float acc[4][4][4];
    #pragma unroll
    for (int i = 0; i < 4; i++)
        #pragma unroll
        for (int j = 0; j < 4; j++)
            #pragma unroll
            for (int e = 0; e < 4; e++) acc[i][j][e] = 0.0f;

    issue(0, 0);

    for (int kt = 0; kt < NK; kt++) {
        asm volatile("cp.async.wait_group 0;\n" ::: "memory");
        __syncthreads();
        if (kt + 1 < NK) issue((kt + 1) & 1, kt + 1);

        const int buf = kt & 1;
        const uint32_t abase = asmem + buf * A_STAGE_B;
        const uint32_t bbase = bsmem + buf * B_STAGE_B;

        #pragma unroll
        for (int ks = 0; ks < 2; ks++) {
            const int ko = ks * 16;
            uint32_t areg[4][4];
            #pragma unroll
            for (int fm = 0; fm < 4; fm++) {
                const int row = wm + fm * 16 + (lane & 15);
                const int col = ko + (lane >> 4) * 8;
                ldsm4(areg[fm], abase + (uint32_t)(row * ASTRIDE + col) * 2);
            }
            uint32_t breg[4][2];
            #pragma unroll
            for (int fp = 0; fp < 2; fp++) {
                const int r  = ko + (lane & 15);
                const int cn = wn + fp * 16 + (lane >> 4) * 8;
                uint32_t t[4];
                ldsm4t(t, bbase + (uint32_t)(r * BSTRIDE + cn) * 2);
                breg[fp * 2][0]     = t[0]; breg[fp * 2][1]     = t[1];
                breg[fp * 2 + 1][0] = t[2]; breg[fp * 2 + 1][1] = t[3];
            }
            #pragma unroll
            for (int fm = 0; fm < 4; fm++)
                #pragma unroll
                for (int fn = 0; fn < 4; fn++)
                    mma16816(acc[fm][fn], areg[fm], breg[fn][0], breg[fn][1]);
        }
        __syncthreads();
    }

    // Epilogue: bias + LeakyReLU(0.2), fp32 stores (float2)
    const int g   = lane >> 2;
    const int tig = lane & 3;
    #pragma unroll
    for (int fm = 0; fm < 4; fm++) {
        const int fo = m0 + wm + fm * 16 + g;
        const float bv0 = __ldg(bias + fo);
        const float bv1 = __ldg(bias + fo + 8);
        const size_t ob0 = (((size_t)bb * FO + fo) * OHW + oh) * OHW;
        const size_t ob1 = ob0 + (size_t)8 * OHW * OHW;
        #pragma unroll
        for (int fn = 0; fn < 4; fn++) {
            const int ow = wn + fn * 8 + tig * 2;
            float v0 = acc[fm][fn][0] + bv0;
            float v1 = acc[fm][fn][1] + bv0;
            float v2 = acc[fm][fn][2] + bv1;
            float v3 = acc[fm][fn][3] + bv1;
            v0 = (v0 >= 0.0f) ? v0 : 0.2f * v0;
            v1 = (v1 >= 0.0f) ? v1 : 0.2f * v1;
            v2 = (v2 >= 0.0f) ? v2 : 0.2f * v2;
            v3 = (v3 >= 0.0f) ? v3 : 0.2f * v3;
            float2 p0 = make_float2(v0, v1);
            float2 p1 = make_float2(v2, v3);
            *reinterpret_cast<float2*>(out + ob0 + ow) = p0;
            *reinterpret_cast<float2*>(out + ob1 + ow) = p1;
        }
    }
}

// ---------------------------------------------------------------------------
// Launch
// ---------------------------------------------------------------------------
extern "C" void kernel_launch(void* const* d_in, const int* in_sizes, int n_in,
                              void* d_out, int out_size) {
    const float *x = nullptr, *w = nullptr, *b = nullptr, *fir = nullptr;
    for (int i = 0; i < n_in; i++) {
        switch (in_sizes[i]) {
            case 134217728: x   = (const float*)d_in[i]; break;  // (8,256,256,256)
            case 1179648:   w   = (const float*)d_in[i]; break;  // (512,256,3,3)
            case 512:       b   = (const float*)d_in[i]; break;  // (1,512,1,1)
            case 16:        fir = (const float*)d_in[i]; break;  // (4,4)
        }
    }
    float* out = (float*)d_out;

    fir_kernel<<<dim3(33, 2048), 256>>>(x, fir);
    wcvt_kernel<<<(FO * KTOT + 255) / 256, 256>>>(w);
    conv_gemm_kernel<<<dim3(FO / BM, BATCH * OHW), 256>>>(b, out);
}